// round 14
// baseline (speedup 1.0000x reference)
#include <cuda_runtime.h>
#include <cuda_fp16.h>
#include <cstdint>
#include <cstddef>

// Problem constants
#define BB 2
#define TT 2048
#define CC 2048
#define HH 16
#define DH 128
#define M_ROWS (BB*TT)          // 4096
#define QKV_N  (3*CC)           // 6144

// Scratch (allocation-free rule: __device__ globals)
__device__ __half g_xh  [(size_t)M_ROWS * CC];      // x fp16        16 MB
__device__ __half g_qkvh[(size_t)M_ROWS * QKV_N];   // qkv fp16      48 MB
__device__ __half g_yh  [(size_t)M_ROWS * CC];      // attn out fp16 16 MB
__device__ __half g_wath[(size_t)QKV_N * CC];       // W_attn^T fp16 24 MB
__device__ __half g_wpth[(size_t)CC * CC];          // W_proj^T fp16  8 MB

// ---------------------------------------------------------------------------
// PTX helpers (all plain sm_80+)
// ---------------------------------------------------------------------------
__device__ __forceinline__ void mma_h(float* c, const uint32_t* a, const uint32_t* b) {
    asm volatile(
        "mma.sync.aligned.m16n8k16.row.col.f32.f16.f16.f32 "
        "{%0,%1,%2,%3}, {%4,%5,%6,%7}, {%8,%9}, {%0,%1,%2,%3};"
        : "+f"(c[0]), "+f"(c[1]), "+f"(c[2]), "+f"(c[3])
        : "r"(a[0]), "r"(a[1]), "r"(a[2]), "r"(a[3]), "r"(b[0]), "r"(b[1]));
}

__device__ __forceinline__ uint32_t pack_h2(float lo, float hi) {
    __half2 h = __floats2half2_rn(lo, hi);
    return *(uint32_t*)&h;
}

__device__ __forceinline__ uint32_t smem_u32(const void* p) {
    uint32_t a;
    asm("{ .reg .u64 t; cvta.to.shared.u64 t, %1; cvt.u32.u64 %0, t; }"
        : "=r"(a) : "l"(p));
    return a;
}

__device__ __forceinline__ void ldsm_x4(uint32_t* r, uint32_t addr) {
    asm volatile("ldmatrix.sync.aligned.m8n8.x4.shared.b16 {%0,%1,%2,%3}, [%4];"
                 : "=r"(r[0]), "=r"(r[1]), "=r"(r[2]), "=r"(r[3]) : "r"(addr));
}

__device__ __forceinline__ void ldsm_x4_t(uint32_t* r, uint32_t addr) {
    asm volatile("ldmatrix.sync.aligned.m8n8.x4.trans.shared.b16 {%0,%1,%2,%3}, [%4];"
                 : "=r"(r[0]), "=r"(r[1]), "=r"(r[2]), "=r"(r[3]) : "r"(addr));
}

__device__ __forceinline__ void cp16(uint32_t saddr, const void* gaddr) {
    asm volatile("cp.async.cg.shared.global [%0], [%1], 16;"
                 :: "r"(saddr), "l"(gaddr));
}
#define CP_COMMIT() asm volatile("cp.async.commit_group;" ::: "memory")
#define CP_WAIT1()  asm volatile("cp.async.wait_group 1;" ::: "memory")
#define CP_WAIT0()  asm volatile("cp.async.wait_group 0;" ::: "memory")

// ---------------------------------------------------------------------------
// Pre-pass: f32 -> f16 convert
// ---------------------------------------------------------------------------
__global__ __launch_bounds__(256)
void f2h_kernel(const float* __restrict__ in, __half* __restrict__ out) {
    size_t i = (size_t)blockIdx.x * 256 + threadIdx.x;
    float4 v = ((const float4*)in)[i];
    uint2 o;
    o.x = pack_h2(v.x, v.y);
    o.y = pack_h2(v.z, v.w);
    ((uint2*)out)[i] = o;
}

// ---------------------------------------------------------------------------
// Pre-pass: transpose + convert: in [R][Cn] f32 -> out [Cn][R] f16
// ---------------------------------------------------------------------------
__global__ void trans_h_kernel(const float* __restrict__ in, __half* __restrict__ out,
                               int R, int Cn) {
    __shared__ float t[32][33];
    int bx = blockIdx.x * 32, by = blockIdx.y * 32;
    int tx = threadIdx.x, ty = threadIdx.y;   // (32, 8)
#pragma unroll
    for (int j = 0; j < 32; j += 8)
        t[ty + j][tx] = in[(size_t)(by + ty + j) * Cn + bx + tx];
    __syncthreads();
#pragma unroll
    for (int j = 0; j < 32; j += 8)
        out[(size_t)(bx + ty + j) * R + by + tx] = __float2half_rn(t[tx][ty + j]);
}

// ---------------------------------------------------------------------------
// fp16 GEMM, persistent-CTA with CONTINUOUS cross-tile cp.async pipeline.
// C[M,N] = A[M,2048]h @ Bt[N,2048]h^T + bias[N]. BM=BN=128, BK=64.
// 256 thr, 8 warps (4m x 2n), warp tile 32x64. 3 stages; stage = u%3 where
// u is the global chunk sequence index (no drain at tile boundaries).
// ---------------------------------------------------------------------------
#define GBM 128
#define GBN 128
#define GBK 64
#define KK 2048
#define NCC 32                           // KK / GBK
#define ROWU4G 256                       // KK / 8
#define AROW 36
#define G_TILE (128 * AROW)
#define STAGES 3
#define GEMM_SMEM (2 * STAGES * G_TILE * 4)   // 110592 B
#define PERSIST_CTAS 296

__global__ __launch_bounds__(256, 2)
void h_gemm_kernel(const __half* __restrict__ A, const __half* __restrict__ Bt,
                   const float* __restrict__ bias,
                   float* __restrict__ Cf, __half* __restrict__ Ch,
                   float* __restrict__ cache,
                   int N, int tiles) {
    extern __shared__ uint32_t smu[];
    const uint32_t sbase = smem_u32(smu);
    const uint32_t sA = sbase;
    const uint32_t sB = sbase + STAGES * G_TILE * 4;

    const int tid  = threadIdx.x;
    const int wid  = tid >> 5;
    const int lane = tid & 31;
    const int g    = lane >> 2;
    const int tg   = lane & 3;
    const int wm   = (wid & 3) * 32;
    const int wn   = (wid >> 2) * 64;
    const int gn   = N / GBN;

    const int ntiles_own = (tiles - (int)blockIdx.x + (int)gridDim.x - 1) / (int)gridDim.x;
    if (ntiles_own <= 0) return;
    const int U = ntiles_own * NCC;

    // Per-thread tile-invariant coords
    int lrA[4], lc4[4]; uint32_t so[4];
#pragma unroll
    for (int i = 0; i < 4; i++) {
        int idx = i * 256 + tid;
        lrA[i] = idx >> 3; lc4[i] = idx & 7;
        so[i] = (uint32_t)(lrA[i] * AROW + lc4[i] * 4) * 4;
    }

    const int mrow = lane & 7;
    const int msel = lane >> 3;
    uint32_t aOff[2];
#pragma unroll
    for (int i = 0; i < 2; i++)
        aOff[i] = (uint32_t)(((wm + 16 * i + (msel & 1) * 8 + mrow) * AROW
                             + (msel >> 1) * 4) * 4);
    uint32_t bOff[4];
#pragma unroll
    for (int jj = 0; jj < 4; jj++)
        bOff[jj] = (uint32_t)(((wn + 16 * jj + (msel >> 1) * 8 + mrow) * AROW
                              + (msel & 1) * 4) * 4);

    const uint4* A4 = (const uint4*)A;
    const uint4* B4 = (const uint4*)Bt;

    // prefetch chunk with global sequence index v into stage v%3
    auto prefetch = [&](int v) {
        const int tv  = (int)blockIdx.x + (v / NCC) * (int)gridDim.x;
        const int chv = v % NCC;
        const int m0v = (tv / gn) * GBM;
        const int n0v = (tv % gn) * GBN;
        const int st  = v % STAGES;
        const uint32_t aS = sA + st * G_TILE * 4;
        const uint32_t bS = sB + st * G_TILE * 4;
#pragma unroll
        for (int i = 0; i < 4; i++) {
            cp16(aS + so[i], A4 + (size_t)(m0v + lrA[i]) * ROWU4G + chv * 8 + lc4[i]);
            cp16(bS + so[i], B4 + (size_t)(n0v + lrA[i]) * ROWU4G + chv * 8 + lc4[i]);
        }
        CP_COMMIT();
    };

    // Prologue: chunks 0, 1 (U >= NCC = 32 always)
    prefetch(0);
    prefetch(1);

    float c[2][8][4];
    int m0 = 0, n0 = 0;

    for (int u = 0; u < U; ++u) {
        const int ch = u % NCC;
        if (ch == 0) {
            const int t = (int)blockIdx.x + (u / NCC) * (int)gridDim.x;
            m0 = (t / gn) * GBM;
            n0 = (t % gn) * GBN;
#pragma unroll
            for (int i = 0; i < 2; i++)
#pragma unroll
                for (int j = 0; j < 8; j++)
#pragma unroll
                    for (int q = 0; q < 4; q++) c[i][j][q] = 0.0f;
        }

        if (u + 1 < U) { CP_WAIT1(); } else { CP_WAIT0(); }
        __syncthreads();   // chunk u visible; stage (u+2)%3 free for refill

        if (u + 2 < U) prefetch(u + 2);

        const int cur = u % STAGES;
        const uint32_t aS = sA + cur * G_TILE * 4;
        const uint32_t bS = sB + cur * G_TILE * 4;

#pragma unroll
        for (int s = 0; s < 4; s++) {
            uint32_t a[2][4], bq[4][4];
#pragma unroll
            for (int i = 0; i < 2; i++)
                ldsm_x4(a[i], aS + aOff[i] + s * 32);
#pragma unroll
            for (int jj = 0; jj < 4; jj++)
                ldsm_x4(bq[jj], bS + bOff[jj] + s * 32);
#pragma unroll
            for (int i = 0; i < 2; i++)
#pragma unroll
                for (int jj = 0; jj < 4; jj++) {
                    mma_h(c[i][2 * jj],     a[i], &bq[jj][0]);
                    mma_h(c[i][2 * jj + 1], a[i], &bq[jj][2]);
                }
        }

        if (ch == NCC - 1) {
            // Epilogue: register->global only (no smem); overlaps in-flight loads
#pragma unroll
            for (int i = 0; i < 2; i++) {
                int row = m0 + wm + 16 * i + g;
#pragma unroll
                for (int j = 0; j < 8; j++) {
                    int col = n0 + wn + 8 * j + 2 * tg;
                    float2 bv = *(const float2*)(bias + col);
                    float2 o0, o1;
                    o0.x = c[i][j][0] + bv.x;  o0.y = c[i][j][1] + bv.y;
                    o1.x = c[i][j][2] + bv.x;  o1.y = c[i][j][3] + bv.y;
                    if (Cf != nullptr) {
                        *(float2*)(Cf + (size_t)row * N + col) = o0;
                        *(float2*)(Cf + (size_t)(row + 8) * N + col) = o1;
                    }
                    if (Ch != nullptr) {
                        *(uint32_t*)(Ch + (size_t)row * N + col) = pack_h2(o0.x, o0.y);
                        *(uint32_t*)(Ch + (size_t)(row + 8) * N + col) = pack_h2(o1.x, o1.y);
                    }
                    if (cache != nullptr && col >= CC) {
                        int cc = col - CC;
                        *(float2*)(cache + (size_t)row * (2 * CC) + cc) = o0;
                        *(float2*)(cache + (size_t)(row + 8) * (2 * CC) + cc) = o1;
                    }
                }
            }
        }
    }
}

// ---------------------------------------------------------------------------
// Flash attention, fp16 mma (causal) — byte-identical to R12 (protected win).
// P in registers; K/V double-buffered via cp.async.
// ---------------------------------------------------------------------------
#define AQW 68
#define KV_TILE (64 * AQW)
#define ATTN_SMEM_U32 (128 * AQW + 4 * KV_TILE)
#define ATTN_SMEM_BYTES (ATTN_SMEM_U32 * 4)

__global__ __launch_bounds__(256, 2)
void attn_h_kernel(const __half* __restrict__ qkv, __half* __restrict__ y) {
    extern __shared__ uint32_t smu[];
    uint32_t* Qs = smu;

    const uint32_t sbase = smem_u32(smu);
    const uint32_t sQ  = sbase;
    const uint32_t sKV = sbase + 128 * AQW * 4;

    const int tid  = threadIdx.x;
    const int wid  = tid >> 5;
    const int lane = tid & 31;
    const int g    = lane >> 2;
    const int tg   = lane & 3;
    const int bh   = blockIdx.x;
    const int b    = bh >> 4;
    const int h    = bh & 15;
    const int qt   = gridDim.y - 1 - blockIdx.y;
    const int q0   = qt * 128;
    const int wr0  = wid * 16;

    const float SCALE = 0.08838834764831845f;
    const int ROWU4 = QKV_N / 8;

    const uint4* qkv4 = (const uint4*)qkv;
    const size_t bbase = (size_t)b * TT * ROWU4;
    const int qoff = h * 16;
    const int koff = 256 + h * 16;
    const int voff = 512 + h * 16;

    int kvr[4], kvc[4]; uint32_t kvso[4];
#pragma unroll
    for (int p = 0; p < 4; p++) {
        int i = tid + 256 * p;
        kvr[p] = i >> 4; kvc[p] = i & 15;
        kvso[p] = (uint32_t)(kvr[p] * AQW + kvc[p] * 4) * 4;
    }

    const int mrow = lane & 7;
    const int msel = lane >> 3;
    const uint32_t qOff = (uint32_t)(((wr0 + (msel & 1) * 8 + mrow) * AQW
                                     + (msel >> 1) * 4) * 4);
    uint32_t kOff[4];
#pragma unroll
    for (int jj = 0; jj < 4; jj++)
        kOff[jj] = (uint32_t)(((16 * jj + (msel >> 1) * 8 + mrow) * AQW
                              + (msel & 1) * 4) * 4);
    uint32_t vOff[8];
#pragma unroll
    for (int v = 0; v < 8; v++)
        vOff[v] = (uint32_t)((((msel & 1) * 8 + mrow) * AQW
                             + (2 * v + (msel >> 1)) * 4) * 4);

#pragma unroll
    for (int p = 0; p < 8; p++) {
        int i = tid + 256 * p;
        int r = i >> 4, c4 = i & 15;
        uint4 v = qkv4[bbase + (size_t)(q0 + r) * ROWU4 + qoff + c4];
        *(uint4*)&Qs[r * AQW + c4 * 4] = v;
    }

    float m_prev[2] = {-1e30f, -1e30f};
    float l_acc[2]  = {0.0f, 0.0f};
    float acc[16][4];
#pragma unroll
    for (int nj = 0; nj < 16; nj++)
#pragma unroll
        for (int q = 0; q < 4; q++) acc[nj][q] = 0.0f;

    const int ntiles = 2 * qt + 2;

    {
        uint32_t kS = sKV;
        uint32_t vS = sKV + KV_TILE * 4;
#pragma unroll
        for (int p = 0; p < 4; p++) {
            const uint4* src = qkv4 + bbase + (size_t)kvr[p] * ROWU4;
            cp16(kS + kvso[p], src + koff + kvc[p]);
            cp16(vS + kvso[p], src + voff + kvc[p]);
        }
        CP_COMMIT();
    }

    for (int kt = 0; kt < ntiles; ++kt) {
        CP_WAIT0();
        __syncthreads();

        if (kt + 1 < ntiles) {
            const int nk0 = (kt + 1) * 64;
            uint32_t kS = sKV + (uint32_t)(((kt + 1) & 1) * 2 * KV_TILE) * 4;
            uint32_t vS = kS + KV_TILE * 4;
#pragma unroll
            for (int p = 0; p < 4; p++) {
                const uint4* src = qkv4 + bbase + (size_t)(nk0 + kvr[p]) * ROWU4;
                cp16(kS + kvso[p], src + koff + kvc[p]);
                cp16(vS + kvso[p], src + voff + kvc[p]);
            }
            CP_COMMIT();
        }

        const int k0 = kt * 64;
        const uint32_t sK = sKV + (uint32_t)((kt & 1) * 2 * KV_TILE) * 4;
        const uint32_t sV = sK + KV_TILE * 4;

        float cs[8][4];
#pragma unroll
        for (int j = 0; j < 8; j++)
#pragma unroll
            for (int q = 0; q < 4; q++) cs[j][q] = 0.0f;

#pragma unroll
        for (int s = 0; s < 8; s++) {
            uint32_t a[4], bq[4][4];
            ldsm_x4(a, sQ + qOff + s * 32);
#pragma unroll
            for (int jj = 0; jj < 4; jj++)
                ldsm_x4(bq[jj], sK + kOff[jj] + s * 32);
#pragma unroll
            for (int jj = 0; jj < 4; jj++) {
                mma_h(cs[2 * jj],     a, &bq[jj][0]);
                mma_h(cs[2 * jj + 1], a, &bq[jj][2]);
            }
        }

        const int gr0 = q0 + wr0 + g;
        const int gr1 = gr0 + 8;
        float mx0 = -1e30f, mx1 = -1e30f;
#pragma unroll
        for (int j = 0; j < 8; j++) {
            int gc0 = k0 + 8 * j + 2 * tg;
            int gc1 = gc0 + 1;
            float s0 = cs[j][0] * SCALE; if (gc0 > gr0) s0 = -1e30f;
            float s1 = cs[j][1] * SCALE; if (gc1 > gr0) s1 = -1e30f;
            float s2 = cs[j][2] * SCALE; if (gc0 > gr1) s2 = -1e30f;
            float s3 = cs[j][3] * SCALE; if (gc1 > gr1) s3 = -1e30f;
            cs[j][0] = s0; cs[j][1] = s1; cs[j][2] = s2; cs[j][3] = s3;
            mx0 = fmaxf(mx0, fmaxf(s0, s1));
            mx1 = fmaxf(mx1, fmaxf(s2, s3));
        }
        mx0 = fmaxf(mx0, __shfl_xor_sync(0xffffffffu, mx0, 1));
        mx0 = fmaxf(mx0, __shfl_xor_sync(0xffffffffu, mx0, 2));
        mx1 = fmaxf(mx1, __shfl_xor_sync(0xffffffffu, mx1, 1));
        mx1 = fmaxf(mx1, __shfl_xor_sync(0xffffffffu, mx1, 2));

        float mn0 = fmaxf(m_prev[0], mx0);
        float mn1 = fmaxf(m_prev[1], mx1);
        float f0 = __expf(m_prev[0] - mn0);
        float f1 = __expf(m_prev[1] - mn1);
        m_prev[0] = mn0; m_prev[1] = mn1;

        uint32_t a_pv[4][4];
        float ls0 = 0.0f, ls1 = 0.0f;
#pragma unroll
        for (int s = 0; s < 4; s++) {
#pragma unroll
            for (int half = 0; half < 2; half++) {
                int j = 2 * s + half;
                float p0 = __expf(cs[j][0] - mn0);
                float p1 = __expf(cs[j][1] - mn0);
                float p2 = __expf(cs[j][2] - mn1);
                float p3 = __expf(cs[j][3] - mn1);
                ls0 += p0 + p1;
                ls1 += p2 + p3;
                a_pv[s][2 * half]     = pack_h2(p0, p1);
                a_pv[s][2 * half + 1] = pack_h2(p2, p3);
            }
        }
        ls0 += __shfl_xor_sync(0xffffffffu, ls0, 1);
        ls0 += __shfl_xor_sync(0xffffffffu, ls0, 2);
        ls1 += __shfl_xor_sync(0xffffffffu, ls1, 1);
        ls1 += __shfl_xor_sync(0xffffffffu, ls1, 2);
        l_acc[0] = l_acc[0] * f0 + ls0;
        l_acc[1] = l_acc[1] * f1 + ls1;

#pragma unroll
        for (int nj = 0; nj < 16; nj++) {
            acc[nj][0] *= f0; acc[nj][1] *= f0;
            acc[nj][2] *= f1; acc[nj][3] *= f1;
        }

#pragma unroll
        for (int s = 0; s < 4; s++) {
            const uint32_t vsbase = sV + (uint32_t)(s * 16 * AQW * 4);
#pragma unroll
            for (int v = 0; v < 8; v++) {
                uint32_t bq[4];
                ldsm_x4_t(bq, vsbase + vOff[v]);
                mma_h(acc[2 * v],     a_pv[s], &bq[0]);
                mma_h(acc[2 * v + 1], a_pv[s], &bq[2]);
            }
        }
    }

    float inv0 = 1.0f / l_acc[0];
    float inv1 = 1.0f / l_acc[1];
    size_t row0 = (size_t)(b * TT + q0 + wr0 + g);
    size_t row1 = row0 + 8;
#pragma unroll
    for (int nj = 0; nj < 16; nj++) {
        int col = h * DH + 8 * nj + 2 * tg;
        *(uint32_t*)(y + row0 * CC + col) = pack_h2(acc[nj][0] * inv0, acc[nj][1] * inv0);
        *(uint32_t*)(y + row1 * CC + col) = pack_h2(acc[nj][2] * inv1, acc[nj][3] * inv1);
    }
}

// ---------------------------------------------------------------------------
extern "C" void kernel_launch(void* const* d_in, const int* in_sizes, int n_in,
                              void* d_out, int out_size) {
    (void)in_sizes; (void)n_in; (void)out_size;
    const float* x      = (const float*)d_in[0];
    const float* W_attn = (const float*)d_in[2];
    const float* b_attn = (const float*)d_in[3];
    const float* W_proj = (const float*)d_in[4];
    const float* b_proj = (const float*)d_in[5];

    float* out   = (float*)d_out;
    float* y_out = out;
    float* cache = out + (size_t)M_ROWS * CC;

    __half *xh, *qkvh, *yh, *wath, *wpth;
    cudaGetSymbolAddress((void**)&xh,   g_xh);
    cudaGetSymbolAddress((void**)&qkvh, g_qkvh);
    cudaGetSymbolAddress((void**)&yh,   g_yh);
    cudaGetSymbolAddress((void**)&wath, g_wath);
    cudaGetSymbolAddress((void**)&wpth, g_wpth);

    cudaFuncSetAttribute(h_gemm_kernel,
                         cudaFuncAttributeMaxDynamicSharedMemorySize, GEMM_SMEM);
    cudaFuncSetAttribute(attn_h_kernel,
                         cudaFuncAttributeMaxDynamicSharedMemorySize, ATTN_SMEM_BYTES);

    // 0) pre-pass conversions
    f2h_kernel<<<(int)((size_t)M_ROWS * CC / 4 / 256), 256>>>(x, xh);
    {
        dim3 blk(32, 8);
        trans_h_kernel<<<dim3(QKV_N / 32, CC / 32), blk>>>(W_attn, wath, CC, QKV_N);
        trans_h_kernel<<<dim3(CC / 32, CC / 32), blk>>>(W_proj, wpth, CC, CC);
    }
    // 1) qkv = x @ W_attn + b_attn (persistent, continuous pipeline; 1536 tiles)
    {
        int tiles = (QKV_N / GBN) * (M_ROWS / GBM);
        h_gemm_kernel<<<PERSIST_CTAS, 256, GEMM_SMEM>>>(xh, wath, b_attn,
                                                        nullptr, qkvh, cache,
                                                        QKV_N, tiles);
    }
    // 2) flash attention fp16 -> yh
    {
        dim3 grid(BB * HH, TT / 128);           // (32, 16)
        attn_h_kernel<<<grid, 256, ATTN_SMEM_BYTES>>>(qkvh, yh);
    }
    // 3) y = yh @ W_proj + b_proj (persistent; 512 tiles)
    {
        int tiles = (CC / GBN) * (M_ROWS / GBM);
        h_gemm_kernel<<<PERSIST_CTAS, 256, GEMM_SMEM>>>(yh, wpth, b_proj,
                                                        y_out, nullptr, nullptr,
                                                        CC, tiles);
    }
}

// round 15
// speedup vs baseline: 1.0890x; 1.0890x over previous
#include <cuda_runtime.h>
#include <cuda_fp16.h>
#include <cstdint>
#include <cstddef>

// Problem constants
#define BB 2
#define TT 2048
#define CC 2048
#define HH 16
#define DH 128
#define M_ROWS (BB*TT)          // 4096
#define QKV_N  (3*CC)           // 6144

// Scratch (allocation-free rule: __device__ globals)
__device__ __half g_xh  [(size_t)M_ROWS * CC];      // x fp16        16 MB
__device__ __half g_qkvh[(size_t)M_ROWS * QKV_N];   // qkv fp16      48 MB
__device__ __half g_yh  [(size_t)M_ROWS * CC];      // attn out fp16 16 MB
__device__ __half g_wath[(size_t)QKV_N * CC];       // W_attn^T fp16 24 MB
__device__ __half g_wpth[(size_t)CC * CC];          // W_proj^T fp16  8 MB

// ---------------------------------------------------------------------------
// PTX helpers (all plain sm_80+)
// ---------------------------------------------------------------------------
__device__ __forceinline__ void mma_h(float* c, const uint32_t* a, const uint32_t* b) {
    asm volatile(
        "mma.sync.aligned.m16n8k16.row.col.f32.f16.f16.f32 "
        "{%0,%1,%2,%3}, {%4,%5,%6,%7}, {%8,%9}, {%0,%1,%2,%3};"
        : "+f"(c[0]), "+f"(c[1]), "+f"(c[2]), "+f"(c[3])
        : "r"(a[0]), "r"(a[1]), "r"(a[2]), "r"(a[3]), "r"(b[0]), "r"(b[1]));
}

__device__ __forceinline__ uint32_t pack_h2(float lo, float hi) {
    __half2 h = __floats2half2_rn(lo, hi);
    return *(uint32_t*)&h;
}

__device__ __forceinline__ uint32_t smem_u32(const void* p) {
    uint32_t a;
    asm("{ .reg .u64 t; cvta.to.shared.u64 t, %1; cvt.u32.u64 %0, t; }"
        : "=r"(a) : "l"(p));
    return a;
}

__device__ __forceinline__ void ldsm_x4(uint32_t* r, uint32_t addr) {
    asm volatile("ldmatrix.sync.aligned.m8n8.x4.shared.b16 {%0,%1,%2,%3}, [%4];"
                 : "=r"(r[0]), "=r"(r[1]), "=r"(r[2]), "=r"(r[3]) : "r"(addr));
}

__device__ __forceinline__ void ldsm_x4_t(uint32_t* r, uint32_t addr) {
    asm volatile("ldmatrix.sync.aligned.m8n8.x4.trans.shared.b16 {%0,%1,%2,%3}, [%4];"
                 : "=r"(r[0]), "=r"(r[1]), "=r"(r[2]), "=r"(r[3]) : "r"(addr));
}

__device__ __forceinline__ void cp16(uint32_t saddr, const void* gaddr) {
    asm volatile("cp.async.cg.shared.global [%0], [%1], 16;"
                 :: "r"(saddr), "l"(gaddr));
}
#define CP_COMMIT() asm volatile("cp.async.commit_group;" ::: "memory")
#define CP_WAIT1()  asm volatile("cp.async.wait_group 1;" ::: "memory")
#define CP_WAIT0()  asm volatile("cp.async.wait_group 0;" ::: "memory")

// ---------------------------------------------------------------------------
// Pre-pass: f32 -> f16 convert
// ---------------------------------------------------------------------------
__global__ __launch_bounds__(256)
void f2h_kernel(const float* __restrict__ in, __half* __restrict__ out) {
    size_t i = (size_t)blockIdx.x * 256 + threadIdx.x;
    float4 v = ((const float4*)in)[i];
    uint2 o;
    o.x = pack_h2(v.x, v.y);
    o.y = pack_h2(v.z, v.w);
    ((uint2*)out)[i] = o;
}

// ---------------------------------------------------------------------------
// Pre-pass: transpose + convert: in [R][Cn] f32 -> out [Cn][R] f16
// ---------------------------------------------------------------------------
__global__ void trans_h_kernel(const float* __restrict__ in, __half* __restrict__ out,
                               int R, int Cn) {
    __shared__ float t[32][33];
    int bx = blockIdx.x * 32, by = blockIdx.y * 32;
    int tx = threadIdx.x, ty = threadIdx.y;   // (32, 8)
#pragma unroll
    for (int j = 0; j < 32; j += 8)
        t[ty + j][tx] = in[(size_t)(by + ty + j) * Cn + bx + tx];
    __syncthreads();
#pragma unroll
    for (int j = 0; j < 32; j += 8)
        out[(size_t)(bx + ty + j) * R + by + tx] = __float2half_rn(t[tx][ty + j]);
}

// ---------------------------------------------------------------------------
// fp16 GEMM (byte-identical to R11/R12 — proven best):
// BM=BN=128, BK=64, 256 thr, 3-stage cp.async, ldmatrix fragments.
// ---------------------------------------------------------------------------
#define GBM 128
#define GBN 128
#define GBK 64
#define AROW 36
#define G_TILE (128 * AROW)
#define STAGES 3
#define GEMM_SMEM (2 * STAGES * G_TILE * 4)   // 110592 B

__global__ __launch_bounds__(256, 2)
void h_gemm_kernel(const __half* __restrict__ A, const __half* __restrict__ Bt,
                   const float* __restrict__ bias,
                   float* __restrict__ Cf, __half* __restrict__ Ch,
                   float* __restrict__ cache,
                   int M, int N, int K) {
    extern __shared__ uint32_t smu[];
    const uint32_t sbase = smem_u32(smu);
    const uint32_t sA = sbase;
    const uint32_t sB = sbase + STAGES * G_TILE * 4;

    const int tid  = threadIdx.x;
    const int wid  = tid >> 5;
    const int lane = tid & 31;
    const int g    = lane >> 2;
    const int tg   = lane & 3;
    const int wm   = (wid & 3) * 32;
    const int wn   = (wid >> 2) * 64;
    const int m0   = blockIdx.y * GBM;
    const int n0   = blockIdx.x * GBN;
    const int rowu4 = K / 8;

    const uint4* gA[4]; const uint4* gB[4]; uint32_t so[4];
#pragma unroll
    for (int i = 0; i < 4; i++) {
        int idx = i * 256 + tid;
        int r = idx >> 3, c4 = idx & 7;
        gA[i] = (const uint4*)A + (size_t)(m0 + r) * rowu4 + c4;
        gB[i] = (const uint4*)Bt + (size_t)(n0 + r) * rowu4 + c4;
        so[i] = (uint32_t)(r * AROW + c4 * 4) * 4;
    }

    const int mrow = lane & 7;
    const int msel = lane >> 3;
    uint32_t aOff[2];
#pragma unroll
    for (int i = 0; i < 2; i++)
        aOff[i] = (uint32_t)(((wm + 16 * i + (msel & 1) * 8 + mrow) * AROW
                             + (msel >> 1) * 4) * 4);
    uint32_t bOff[4];
#pragma unroll
    for (int jj = 0; jj < 4; jj++)
        bOff[jj] = (uint32_t)(((wn + 16 * jj + (msel >> 1) * 8 + mrow) * AROW
                              + (msel & 1) * 4) * 4);

    float c[2][8][4];
#pragma unroll
    for (int i = 0; i < 2; i++)
#pragma unroll
        for (int j = 0; j < 8; j++)
#pragma unroll
            for (int q = 0; q < 4; q++) c[i][j][q] = 0.0f;

    const int NC = K / GBK;

#pragma unroll
    for (int st = 0; st < 2; st++) {
        uint32_t aS = sA + st * G_TILE * 4;
        uint32_t bS = sB + st * G_TILE * 4;
#pragma unroll
        for (int i = 0; i < 4; i++) {
            cp16(aS + so[i], gA[i] + st * 8);
            cp16(bS + so[i], gB[i] + st * 8);
        }
        CP_COMMIT();
    }

    for (int ch = 0; ch < NC; ++ch) {
        if (ch + 1 < NC) { CP_WAIT1(); } else { CP_WAIT0(); }
        __syncthreads();

        if (ch + 2 < NC) {
            int st = (ch + 2) % STAGES;
            uint32_t aS = sA + st * G_TILE * 4;
            uint32_t bS = sB + st * G_TILE * 4;
#pragma unroll
            for (int i = 0; i < 4; i++) {
                cp16(aS + so[i], gA[i] + (ch + 2) * 8);
                cp16(bS + so[i], gB[i] + (ch + 2) * 8);
            }
            CP_COMMIT();
        }

        const int cur = ch % STAGES;
        const uint32_t aS = sA + cur * G_TILE * 4;
        const uint32_t bS = sB + cur * G_TILE * 4;

#pragma unroll
        for (int s = 0; s < 4; s++) {
            uint32_t a[2][4], bq[4][4];
#pragma unroll
            for (int i = 0; i < 2; i++)
                ldsm_x4(a[i], aS + aOff[i] + s * 32);
#pragma unroll
            for (int jj = 0; jj < 4; jj++)
                ldsm_x4(bq[jj], bS + bOff[jj] + s * 32);
#pragma unroll
            for (int i = 0; i < 2; i++)
#pragma unroll
                for (int jj = 0; jj < 4; jj++) {
                    mma_h(c[i][2 * jj],     a[i], &bq[jj][0]);
                    mma_h(c[i][2 * jj + 1], a[i], &bq[jj][2]);
                }
        }
    }

#pragma unroll
    for (int i = 0; i < 2; i++) {
        int row = m0 + wm + 16 * i + g;
#pragma unroll
        for (int j = 0; j < 8; j++) {
            int col = n0 + wn + 8 * j + 2 * tg;
            float2 bv = *(const float2*)(bias + col);
            float2 o0, o1;
            o0.x = c[i][j][0] + bv.x;  o0.y = c[i][j][1] + bv.y;
            o1.x = c[i][j][2] + bv.x;  o1.y = c[i][j][3] + bv.y;
            if (Cf != nullptr) {
                *(float2*)(Cf + (size_t)row * N + col) = o0;
                *(float2*)(Cf + (size_t)(row + 8) * N + col) = o1;
            }
            if (Ch != nullptr) {
                *(uint32_t*)(Ch + (size_t)row * N + col) = pack_h2(o0.x, o0.y);
                *(uint32_t*)(Ch + (size_t)(row + 8) * N + col) = pack_h2(o1.x, o1.y);
            }
            if (cache != nullptr && col >= CC) {
                int cc = col - CC;
                *(float2*)(cache + (size_t)row * (2 * CC) + cc) = o0;
                *(float2*)(cache + (size_t)(row + 8) * (2 * CC) + cc) = o1;
            }
        }
    }
}

// ---------------------------------------------------------------------------
// Flash attention, fp16 mma (causal). R12 structure (P in registers, K/V
// double-buffered cp.async) + NEW per-warp unmasked fast path for tiles
// fully below the diagonal (k0+63 <= q0+wr0, warp-uniform branch).
// ---------------------------------------------------------------------------
#define AQW 68
#define KV_TILE (64 * AQW)
#define ATTN_SMEM_U32 (128 * AQW + 4 * KV_TILE)
#define ATTN_SMEM_BYTES (ATTN_SMEM_U32 * 4)

__global__ __launch_bounds__(256, 2)
void attn_h_kernel(const __half* __restrict__ qkv, __half* __restrict__ y) {
    extern __shared__ uint32_t smu[];
    uint32_t* Qs = smu;

    const uint32_t sbase = smem_u32(smu);
    const uint32_t sQ  = sbase;
    const uint32_t sKV = sbase + 128 * AQW * 4;

    const int tid  = threadIdx.x;
    const int wid  = tid >> 5;
    const int lane = tid & 31;
    const int g    = lane >> 2;
    const int tg   = lane & 3;
    const int bh   = blockIdx.x;
    const int b    = bh >> 4;
    const int h    = bh & 15;
    const int qt   = gridDim.y - 1 - blockIdx.y;
    const int q0   = qt * 128;
    const int wr0  = wid * 16;

    const float SCALE = 0.08838834764831845f;
    const int ROWU4 = QKV_N / 8;

    const uint4* qkv4 = (const uint4*)qkv;
    const size_t bbase = (size_t)b * TT * ROWU4;
    const int qoff = h * 16;
    const int koff = 256 + h * 16;
    const int voff = 512 + h * 16;

    int kvr[4], kvc[4]; uint32_t kvso[4];
#pragma unroll
    for (int p = 0; p < 4; p++) {
        int i = tid + 256 * p;
        kvr[p] = i >> 4; kvc[p] = i & 15;
        kvso[p] = (uint32_t)(kvr[p] * AQW + kvc[p] * 4) * 4;
    }

    const int mrow = lane & 7;
    const int msel = lane >> 3;
    const uint32_t qOff = (uint32_t)(((wr0 + (msel & 1) * 8 + mrow) * AQW
                                     + (msel >> 1) * 4) * 4);
    uint32_t kOff[4];
#pragma unroll
    for (int jj = 0; jj < 4; jj++)
        kOff[jj] = (uint32_t)(((16 * jj + (msel >> 1) * 8 + mrow) * AQW
                              + (msel & 1) * 4) * 4);
    uint32_t vOff[8];
#pragma unroll
    for (int v = 0; v < 8; v++)
        vOff[v] = (uint32_t)((((msel & 1) * 8 + mrow) * AQW
                             + (2 * v + (msel >> 1)) * 4) * 4);

#pragma unroll
    for (int p = 0; p < 8; p++) {
        int i = tid + 256 * p;
        int r = i >> 4, c4 = i & 15;
        uint4 v = qkv4[bbase + (size_t)(q0 + r) * ROWU4 + qoff + c4];
        *(uint4*)&Qs[r * AQW + c4 * 4] = v;
    }

    float m_prev[2] = {-1e30f, -1e30f};
    float l_acc[2]  = {0.0f, 0.0f};
    float acc[16][4];
#pragma unroll
    for (int nj = 0; nj < 16; nj++)
#pragma unroll
        for (int q = 0; q < 4; q++) acc[nj][q] = 0.0f;

    const int ntiles = 2 * qt + 2;

    {
        uint32_t kS = sKV;
        uint32_t vS = sKV + KV_TILE * 4;
#pragma unroll
        for (int p = 0; p < 4; p++) {
            const uint4* src = qkv4 + bbase + (size_t)kvr[p] * ROWU4;
            cp16(kS + kvso[p], src + koff + kvc[p]);
            cp16(vS + kvso[p], src + voff + kvc[p]);
        }
        CP_COMMIT();
    }

    for (int kt = 0; kt < ntiles; ++kt) {
        CP_WAIT0();
        __syncthreads();

        if (kt + 1 < ntiles) {
            const int nk0 = (kt + 1) * 64;
            uint32_t kS = sKV + (uint32_t)(((kt + 1) & 1) * 2 * KV_TILE) * 4;
            uint32_t vS = kS + KV_TILE * 4;
#pragma unroll
            for (int p = 0; p < 4; p++) {
                const uint4* src = qkv4 + bbase + (size_t)(nk0 + kvr[p]) * ROWU4;
                cp16(kS + kvso[p], src + koff + kvc[p]);
                cp16(vS + kvso[p], src + voff + kvc[p]);
            }
            CP_COMMIT();
        }

        const int k0 = kt * 64;
        const uint32_t sK = sKV + (uint32_t)((kt & 1) * 2 * KV_TILE) * 4;
        const uint32_t sV = sK + KV_TILE * 4;

        float cs[8][4];
#pragma unroll
        for (int j = 0; j < 8; j++)
#pragma unroll
            for (int q = 0; q < 4; q++) cs[j][q] = 0.0f;

#pragma unroll
        for (int s = 0; s < 8; s++) {
            uint32_t a[4], bq[4][4];
            ldsm_x4(a, sQ + qOff + s * 32);
#pragma unroll
            for (int jj = 0; jj < 4; jj++)
                ldsm_x4(bq[jj], sK + kOff[jj] + s * 32);
#pragma unroll
            for (int jj = 0; jj < 4; jj++) {
                mma_h(cs[2 * jj],     a, &bq[jj][0]);
                mma_h(cs[2 * jj + 1], a, &bq[jj][2]);
            }
        }

        // ---- scale (+causal mask only near the diagonal) + row max ----
        const int gr0 = q0 + wr0 + g;
        const int gr1 = gr0 + 8;
        float mx0 = -1e30f, mx1 = -1e30f;
        if (k0 + 63 <= q0 + wr0) {
            // warp-uniform: entire tile strictly below this warp's rows
#pragma unroll
            for (int j = 0; j < 8; j++) {
                float s0 = cs[j][0] * SCALE;
                float s1 = cs[j][1] * SCALE;
                float s2 = cs[j][2] * SCALE;
                float s3 = cs[j][3] * SCALE;
                cs[j][0] = s0; cs[j][1] = s1; cs[j][2] = s2; cs[j][3] = s3;
                mx0 = fmaxf(mx0, fmaxf(s0, s1));
                mx1 = fmaxf(mx1, fmaxf(s2, s3));
            }
        } else {
#pragma unroll
            for (int j = 0; j < 8; j++) {
                int gc0 = k0 + 8 * j + 2 * tg;
                int gc1 = gc0 + 1;
                float s0 = cs[j][0] * SCALE; if (gc0 > gr0) s0 = -1e30f;
                float s1 = cs[j][1] * SCALE; if (gc1 > gr0) s1 = -1e30f;
                float s2 = cs[j][2] * SCALE; if (gc0 > gr1) s2 = -1e30f;
                float s3 = cs[j][3] * SCALE; if (gc1 > gr1) s3 = -1e30f;
                cs[j][0] = s0; cs[j][1] = s1; cs[j][2] = s2; cs[j][3] = s3;
                mx0 = fmaxf(mx0, fmaxf(s0, s1));
                mx1 = fmaxf(mx1, fmaxf(s2, s3));
            }
        }
        mx0 = fmaxf(mx0, __shfl_xor_sync(0xffffffffu, mx0, 1));
        mx0 = fmaxf(mx0, __shfl_xor_sync(0xffffffffu, mx0, 2));
        mx1 = fmaxf(mx1, __shfl_xor_sync(0xffffffffu, mx1, 1));
        mx1 = fmaxf(mx1, __shfl_xor_sync(0xffffffffu, mx1, 2));

        float mn0 = fmaxf(m_prev[0], mx0);
        float mn1 = fmaxf(m_prev[1], mx1);
        float f0 = __expf(m_prev[0] - mn0);
        float f1 = __expf(m_prev[1] - mn1);
        m_prev[0] = mn0; m_prev[1] = mn1;

        uint32_t a_pv[4][4];
        float ls0 = 0.0f, ls1 = 0.0f;
#pragma unroll
        for (int s = 0; s < 4; s++) {
#pragma unroll
            for (int half = 0; half < 2; half++) {
                int j = 2 * s + half;
                float p0 = __expf(cs[j][0] - mn0);
                float p1 = __expf(cs[j][1] - mn0);
                float p2 = __expf(cs[j][2] - mn1);
                float p3 = __expf(cs[j][3] - mn1);
                ls0 += p0 + p1;
                ls1 += p2 + p3;
                a_pv[s][2 * half]     = pack_h2(p0, p1);
                a_pv[s][2 * half + 1] = pack_h2(p2, p3);
            }
        }
        ls0 += __shfl_xor_sync(0xffffffffu, ls0, 1);
        ls0 += __shfl_xor_sync(0xffffffffu, ls0, 2);
        ls1 += __shfl_xor_sync(0xffffffffu, ls1, 1);
        ls1 += __shfl_xor_sync(0xffffffffu, ls1, 2);
        l_acc[0] = l_acc[0] * f0 + ls0;
        l_acc[1] = l_acc[1] * f1 + ls1;

#pragma unroll
        for (int nj = 0; nj < 16; nj++) {
            acc[nj][0] *= f0; acc[nj][1] *= f0;
            acc[nj][2] *= f1; acc[nj][3] *= f1;
        }

#pragma unroll
        for (int s = 0; s < 4; s++) {
            const uint32_t vsbase = sV + (uint32_t)(s * 16 * AQW * 4);
#pragma unroll
            for (int v = 0; v < 8; v++) {
                uint32_t bq[4];
                ldsm_x4_t(bq, vsbase + vOff[v]);
                mma_h(acc[2 * v],     a_pv[s], &bq[0]);
                mma_h(acc[2 * v + 1], a_pv[s], &bq[2]);
            }
        }
    }

    float inv0 = 1.0f / l_acc[0];
    float inv1 = 1.0f / l_acc[1];
    size_t row0 = (size_t)(b * TT + q0 + wr0 + g);
    size_t row1 = row0 + 8;
#pragma unroll
    for (int nj = 0; nj < 16; nj++) {
        int col = h * DH + 8 * nj + 2 * tg;
        *(uint32_t*)(y + row0 * CC + col) = pack_h2(acc[nj][0] * inv0, acc[nj][1] * inv0);
        *(uint32_t*)(y + row1 * CC + col) = pack_h2(acc[nj][2] * inv1, acc[nj][3] * inv1);
    }
}

// ---------------------------------------------------------------------------
extern "C" void kernel_launch(void* const* d_in, const int* in_sizes, int n_in,
                              void* d_out, int out_size) {
    (void)in_sizes; (void)n_in; (void)out_size;
    const float* x      = (const float*)d_in[0];
    const float* W_attn = (const float*)d_in[2];
    const float* b_attn = (const float*)d_in[3];
    const float* W_proj = (const float*)d_in[4];
    const float* b_proj = (const float*)d_in[5];

    float* out   = (float*)d_out;
    float* y_out = out;
    float* cache = out + (size_t)M_ROWS * CC;

    __half *xh, *qkvh, *yh, *wath, *wpth;
    cudaGetSymbolAddress((void**)&xh,   g_xh);
    cudaGetSymbolAddress((void**)&qkvh, g_qkvh);
    cudaGetSymbolAddress((void**)&yh,   g_yh);
    cudaGetSymbolAddress((void**)&wath, g_wath);
    cudaGetSymbolAddress((void**)&wpth, g_wpth);

    cudaFuncSetAttribute(h_gemm_kernel,
                         cudaFuncAttributeMaxDynamicSharedMemorySize, GEMM_SMEM);
    cudaFuncSetAttribute(attn_h_kernel,
                         cudaFuncAttributeMaxDynamicSharedMemorySize, ATTN_SMEM_BYTES);

    // 0) pre-pass conversions
    f2h_kernel<<<(int)((size_t)M_ROWS * CC / 4 / 256), 256>>>(x, xh);
    {
        dim3 blk(32, 8);
        trans_h_kernel<<<dim3(QKV_N / 32, CC / 32), blk>>>(W_attn, wath, CC, QKV_N);
        trans_h_kernel<<<dim3(CC / 32, CC / 32), blk>>>(W_proj, wpth, CC, CC);
    }
    // 1) qkv = x @ W_attn + b_attn -> qkv fp16 + fused f32 cache
    {
        dim3 grid(QKV_N / GBN, M_ROWS / GBM);   // (48, 32)
        h_gemm_kernel<<<grid, 256, GEMM_SMEM>>>(xh, wath, b_attn,
                                                nullptr, qkvh, cache,
                                                M_ROWS, QKV_N, CC);
    }
    // 2) flash attention fp16 -> yh
    {
        dim3 grid(BB * HH, TT / 128);           // (32, 16)
        attn_h_kernel<<<grid, 256, ATTN_SMEM_BYTES>>>(qkvh, yh);
    }
    // 3) y = yh @ W_proj + b_proj -> f32 out
    {
        dim3 grid(CC / GBN, M_ROWS / GBM);      // (16, 32)
        h_gemm_kernel<<<grid, 256, GEMM_SMEM>>>(yh, wpth, b_proj,
                                                y_out, nullptr, nullptr,
                                                M_ROWS, CC, CC);
    }
}

// round 16
// speedup vs baseline: 1.1007x; 1.0107x over previous
#include <cuda_runtime.h>
#include <cuda_fp16.h>
#include <cstdint>
#include <cstddef>

// Problem constants
#define BB 2
#define TT 2048
#define CC 2048
#define HH 16
#define DH 128
#define M_ROWS (BB*TT)          // 4096
#define QKV_N  (3*CC)           // 6144

// Scratch (allocation-free rule: __device__ globals)
__device__ __half g_xh  [(size_t)M_ROWS * CC];      // x fp16        16 MB
__device__ __half g_qkvh[(size_t)M_ROWS * QKV_N];   // qkv fp16      48 MB
__device__ __half g_yh  [(size_t)M_ROWS * CC];      // attn out fp16 16 MB
__device__ __half g_wah [(size_t)CC * QKV_N];       // W_attn f16 [K][N] 24 MB
__device__ __half g_wph [(size_t)CC * CC];          // W_proj f16 [K][N]  8 MB

// ---------------------------------------------------------------------------
// PTX helpers (all plain sm_80+)
// ---------------------------------------------------------------------------
__device__ __forceinline__ void mma_h(float* c, const uint32_t* a, const uint32_t* b) {
    asm volatile(
        "mma.sync.aligned.m16n8k16.row.col.f32.f16.f16.f32 "
        "{%0,%1,%2,%3}, {%4,%5,%6,%7}, {%8,%9}, {%0,%1,%2,%3};"
        : "+f"(c[0]), "+f"(c[1]), "+f"(c[2]), "+f"(c[3])
        : "r"(a[0]), "r"(a[1]), "r"(a[2]), "r"(a[3]), "r"(b[0]), "r"(b[1]));
}

__device__ __forceinline__ uint32_t pack_h2(float lo, float hi) {
    __half2 h = __floats2half2_rn(lo, hi);
    return *(uint32_t*)&h;
}

__device__ __forceinline__ uint32_t smem_u32(const void* p) {
    uint32_t a;
    asm("{ .reg .u64 t; cvta.to.shared.u64 t, %1; cvt.u32.u64 %0, t; }"
        : "=r"(a) : "l"(p));
    return a;
}

__device__ __forceinline__ void ldsm_x4(uint32_t* r, uint32_t addr) {
    asm volatile("ldmatrix.sync.aligned.m8n8.x4.shared.b16 {%0,%1,%2,%3}, [%4];"
                 : "=r"(r[0]), "=r"(r[1]), "=r"(r[2]), "=r"(r[3]) : "r"(addr));
}

__device__ __forceinline__ void ldsm_x4_t(uint32_t* r, uint32_t addr) {
    asm volatile("ldmatrix.sync.aligned.m8n8.x4.trans.shared.b16 {%0,%1,%2,%3}, [%4];"
                 : "=r"(r[0]), "=r"(r[1]), "=r"(r[2]), "=r"(r[3]) : "r"(addr));
}

__device__ __forceinline__ void cp16(uint32_t saddr, const void* gaddr) {
    asm volatile("cp.async.cg.shared.global [%0], [%1], 16;"
                 :: "r"(saddr), "l"(gaddr));
}
#define CP_COMMIT() asm volatile("cp.async.commit_group;" ::: "memory")
#define CP_WAIT1()  asm volatile("cp.async.wait_group 1;" ::: "memory")
#define CP_WAIT0()  asm volatile("cp.async.wait_group 0;" ::: "memory")

// ---------------------------------------------------------------------------
// Pre-pass: f32 -> f16 convert (elementwise, layout preserved)
// ---------------------------------------------------------------------------
__global__ __launch_bounds__(256)
void f2h_kernel(const float* __restrict__ in, __half* __restrict__ out) {
    size_t i = (size_t)blockIdx.x * 256 + threadIdx.x;
    float4 v = ((const float4*)in)[i];
    uint2 o;
    o.x = pack_h2(v.x, v.y);
    o.y = pack_h2(v.z, v.w);
    ((uint2*)out)[i] = o;
}

// ---------------------------------------------------------------------------
// fp16 GEMM:  C[M,N] = A[M,K]h @ W[K,N]h + bias[N]
// BM=BN=128, BK=64. 256 thr, 8 warps (4m x 2n), warp tile 32x64.
// A: K-major rows (AROW=36 u32), fragments via ldmatrix (non-trans).
// B: native [k][n] rows (BROW=68 u32), fragments via ldmatrix.TRANS
//    (bank pattern + fragment algebra identical to attention PV — validated).
// 3-stage cp.async pipeline.
// ---------------------------------------------------------------------------
#define GBM 128
#define GBN 128
#define GBK 64
#define AROW 36
#define BROW 68
#define A_TILE_U (128 * AROW)            // 4608 u32
#define B_TILE_U (64 * BROW)             // 4352 u32
#define STAGES 3
#define GEMM_SMEM ((A_TILE_U + B_TILE_U) * STAGES * 4)   // 107520 B

__global__ __launch_bounds__(256, 2)
void h_gemm_kernel(const __half* __restrict__ A, const __half* __restrict__ W,
                   const float* __restrict__ bias,
                   float* __restrict__ Cf, __half* __restrict__ Ch,
                   float* __restrict__ cache,
                   int M, int N, int K) {
    extern __shared__ uint32_t smu[];
    const uint32_t sbase = smem_u32(smu);
    const uint32_t sA = sbase;                              // [STAGES][A_TILE_U]
    const uint32_t sB = sbase + STAGES * A_TILE_U * 4;      // [STAGES][B_TILE_U]

    const int tid  = threadIdx.x;
    const int wid  = tid >> 5;
    const int lane = tid & 31;
    const int g    = lane >> 2;
    const int tg   = lane & 3;
    const int wm   = (wid & 3) * 32;
    const int wn   = (wid >> 2) * 64;
    const int m0   = blockIdx.y * GBM;
    const int n0   = blockIdx.x * GBN;
    const int Au4  = K / 8;        // uint4 per A row
    const int Wu4  = N / 8;        // uint4 per W row

    // A cp.async coords: 128 rows x 8 u4 per stage -> 4 per thread
    const uint4* gA[4]; uint32_t soA[4];
#pragma unroll
    for (int i = 0; i < 4; i++) {
        int idx = i * 256 + tid;
        int r = idx >> 3, c4 = idx & 7;
        gA[i] = (const uint4*)A + (size_t)(m0 + r) * Au4 + c4;
        soA[i] = (uint32_t)(r * AROW + c4 * 4) * 4;
    }
    // B cp.async coords: 64 k-rows x 16 u4 (128 halfs) per stage -> 4 per thread
    const uint4* gB[4]; uint32_t soB[4];
#pragma unroll
    for (int i = 0; i < 4; i++) {
        int idx = i * 256 + tid;
        int kr = idx >> 4, c4 = idx & 15;
        gB[i] = (const uint4*)W + (size_t)kr * Wu4 + (n0 >> 3) + c4;
        soB[i] = (uint32_t)(kr * BROW + c4 * 4) * 4;
    }

    // ldmatrix lane addressing
    const int mrow = lane & 7;
    const int msel = lane >> 3;
    uint32_t aOff[2];
#pragma unroll
    for (int i = 0; i < 2; i++)
        aOff[i] = (uint32_t)(((wm + 16 * i + (msel & 1) * 8 + mrow) * AROW
                             + (msel >> 1) * 4) * 4);
    // B trans fragments: k-row (msel&1)*8+mrow (+16 per k-step), n-group jj:
    // u32 col = wn/2 + 8*jj + 4*(msel>>1)
    uint32_t bOff[4];
#pragma unroll
    for (int jj = 0; jj < 4; jj++)
        bOff[jj] = (uint32_t)((((msel & 1) * 8 + mrow) * BROW
                              + (wn >> 1) + 8 * jj + 4 * (msel >> 1)) * 4);

    float c[2][8][4];
#pragma unroll
    for (int i = 0; i < 2; i++)
#pragma unroll
        for (int j = 0; j < 8; j++)
#pragma unroll
            for (int q = 0; q < 4; q++) c[i][j][q] = 0.0f;

    const int NC = K / GBK;

    // Prologue: stages 0, 1
#pragma unroll
    for (int st = 0; st < 2; st++) {
        uint32_t aS = sA + st * A_TILE_U * 4;
        uint32_t bS = sB + st * B_TILE_U * 4;
#pragma unroll
        for (int i = 0; i < 4; i++) {
            cp16(aS + soA[i], gA[i] + st * 8);                       // +64 halfs in K
            cp16(bS + soB[i], gB[i] + (size_t)st * 64 * Wu4);        // +64 k-rows
        }
        CP_COMMIT();
    }

    for (int ch = 0; ch < NC; ++ch) {
        if (ch + 1 < NC) { CP_WAIT1(); } else { CP_WAIT0(); }
        __syncthreads();

        if (ch + 2 < NC) {
            int st = (ch + 2) % STAGES;
            uint32_t aS = sA + st * A_TILE_U * 4;
            uint32_t bS = sB + st * B_TILE_U * 4;
#pragma unroll
            for (int i = 0; i < 4; i++) {
                cp16(aS + soA[i], gA[i] + (ch + 2) * 8);
                cp16(bS + soB[i], gB[i] + (size_t)(ch + 2) * 64 * Wu4);
            }
            CP_COMMIT();
        }

        const int cur = ch % STAGES;
        const uint32_t aS = sA + cur * A_TILE_U * 4;
        const uint32_t bS = sB + cur * B_TILE_U * 4;

#pragma unroll
        for (int s = 0; s < 4; s++) {
            uint32_t a[2][4], bq[4][4];
#pragma unroll
            for (int i = 0; i < 2; i++)
                ldsm_x4(a[i], aS + aOff[i] + s * 32);
            const uint32_t bStep = bS + (uint32_t)(s * 16 * BROW * 4);
#pragma unroll
            for (int jj = 0; jj < 4; jj++)
                ldsm_x4_t(bq[jj], bStep + bOff[jj]);
#pragma unroll
            for (int i = 0; i < 2; i++)
#pragma unroll
                for (int jj = 0; jj < 4; jj++) {
                    mma_h(c[i][2 * jj],     a[i], &bq[jj][0]);
                    mma_h(c[i][2 * jj + 1], a[i], &bq[jj][2]);
                }
        }
    }

    // Epilogue
#pragma unroll
    for (int i = 0; i < 2; i++) {
        int row = m0 + wm + 16 * i + g;
#pragma unroll
        for (int j = 0; j < 8; j++) {
            int col = n0 + wn + 8 * j + 2 * tg;
            float2 bv = *(const float2*)(bias + col);
            float2 o0, o1;
            o0.x = c[i][j][0] + bv.x;  o0.y = c[i][j][1] + bv.y;
            o1.x = c[i][j][2] + bv.x;  o1.y = c[i][j][3] + bv.y;
            if (Cf != nullptr) {
                *(float2*)(Cf + (size_t)row * N + col) = o0;
                *(float2*)(Cf + (size_t)(row + 8) * N + col) = o1;
            }
            if (Ch != nullptr) {
                *(uint32_t*)(Ch + (size_t)row * N + col) = pack_h2(o0.x, o0.y);
                *(uint32_t*)(Ch + (size_t)(row + 8) * N + col) = pack_h2(o1.x, o1.y);
            }
            if (cache != nullptr && col >= CC) {
                int cc = col - CC;
                *(float2*)(cache + (size_t)row * (2 * CC) + cc) = o0;
                *(float2*)(cache + (size_t)(row + 8) * (2 * CC) + cc) = o1;
            }
        }
    }
}

// ---------------------------------------------------------------------------
// Flash attention, fp16 mma (causal) — byte-identical to R15 (protected win).
// P in registers; K/V double-buffered cp.async; warp-uniform unmasked path.
// ---------------------------------------------------------------------------
#define AQW 68
#define KV_TILE (64 * AQW)
#define ATTN_SMEM_U32 (128 * AQW + 4 * KV_TILE)
#define ATTN_SMEM_BYTES (ATTN_SMEM_U32 * 4)

__global__ __launch_bounds__(256, 2)
void attn_h_kernel(const __half* __restrict__ qkv, __half* __restrict__ y) {
    extern __shared__ uint32_t smu[];
    uint32_t* Qs = smu;

    const uint32_t sbase = smem_u32(smu);
    const uint32_t sQ  = sbase;
    const uint32_t sKV = sbase + 128 * AQW * 4;

    const int tid  = threadIdx.x;
    const int wid  = tid >> 5;
    const int lane = tid & 31;
    const int g    = lane >> 2;
    const int tg   = lane & 3;
    const int bh   = blockIdx.x;
    const int b    = bh >> 4;
    const int h    = bh & 15;
    const int qt   = gridDim.y - 1 - blockIdx.y;
    const int q0   = qt * 128;
    const int wr0  = wid * 16;

    const float SCALE = 0.08838834764831845f;
    const int ROWU4 = QKV_N / 8;

    const uint4* qkv4 = (const uint4*)qkv;
    const size_t bbase = (size_t)b * TT * ROWU4;
    const int qoff = h * 16;
    const int koff = 256 + h * 16;
    const int voff = 512 + h * 16;

    int kvr[4], kvc[4]; uint32_t kvso[4];
#pragma unroll
    for (int p = 0; p < 4; p++) {
        int i = tid + 256 * p;
        kvr[p] = i >> 4; kvc[p] = i & 15;
        kvso[p] = (uint32_t)(kvr[p] * AQW + kvc[p] * 4) * 4;
    }

    const int mrow = lane & 7;
    const int msel = lane >> 3;
    const uint32_t qOff = (uint32_t)(((wr0 + (msel & 1) * 8 + mrow) * AQW
                                     + (msel >> 1) * 4) * 4);
    uint32_t kOff[4];
#pragma unroll
    for (int jj = 0; jj < 4; jj++)
        kOff[jj] = (uint32_t)(((16 * jj + (msel >> 1) * 8 + mrow) * AQW
                              + (msel & 1) * 4) * 4);
    uint32_t vOff[8];
#pragma unroll
    for (int v = 0; v < 8; v++)
        vOff[v] = (uint32_t)((((msel & 1) * 8 + mrow) * AQW
                             + (2 * v + (msel >> 1)) * 4) * 4);

#pragma unroll
    for (int p = 0; p < 8; p++) {
        int i = tid + 256 * p;
        int r = i >> 4, c4 = i & 15;
        uint4 v = qkv4[bbase + (size_t)(q0 + r) * ROWU4 + qoff + c4];
        *(uint4*)&Qs[r * AQW + c4 * 4] = v;
    }

    float m_prev[2] = {-1e30f, -1e30f};
    float l_acc[2]  = {0.0f, 0.0f};
    float acc[16][4];
#pragma unroll
    for (int nj = 0; nj < 16; nj++)
#pragma unroll
        for (int q = 0; q < 4; q++) acc[nj][q] = 0.0f;

    const int ntiles = 2 * qt + 2;

    {
        uint32_t kS = sKV;
        uint32_t vS = sKV + KV_TILE * 4;
#pragma unroll
        for (int p = 0; p < 4; p++) {
            const uint4* src = qkv4 + bbase + (size_t)kvr[p] * ROWU4;
            cp16(kS + kvso[p], src + koff + kvc[p]);
            cp16(vS + kvso[p], src + voff + kvc[p]);
        }
        CP_COMMIT();
    }

    for (int kt = 0; kt < ntiles; ++kt) {
        CP_WAIT0();
        __syncthreads();

        if (kt + 1 < ntiles) {
            const int nk0 = (kt + 1) * 64;
            uint32_t kS = sKV + (uint32_t)(((kt + 1) & 1) * 2 * KV_TILE) * 4;
            uint32_t vS = kS + KV_TILE * 4;
#pragma unroll
            for (int p = 0; p < 4; p++) {
                const uint4* src = qkv4 + bbase + (size_t)(nk0 + kvr[p]) * ROWU4;
                cp16(kS + kvso[p], src + koff + kvc[p]);
                cp16(vS + kvso[p], src + voff + kvc[p]);
            }
            CP_COMMIT();
        }

        const int k0 = kt * 64;
        const uint32_t sK = sKV + (uint32_t)((kt & 1) * 2 * KV_TILE) * 4;
        const uint32_t sV = sK + KV_TILE * 4;

        float cs[8][4];
#pragma unroll
        for (int j = 0; j < 8; j++)
#pragma unroll
            for (int q = 0; q < 4; q++) cs[j][q] = 0.0f;

#pragma unroll
        for (int s = 0; s < 8; s++) {
            uint32_t a[4], bq[4][4];
            ldsm_x4(a, sQ + qOff + s * 32);
#pragma unroll
            for (int jj = 0; jj < 4; jj++)
                ldsm_x4(bq[jj], sK + kOff[jj] + s * 32);
#pragma unroll
            for (int jj = 0; jj < 4; jj++) {
                mma_h(cs[2 * jj],     a, &bq[jj][0]);
                mma_h(cs[2 * jj + 1], a, &bq[jj][2]);
            }
        }

        const int gr0 = q0 + wr0 + g;
        const int gr1 = gr0 + 8;
        float mx0 = -1e30f, mx1 = -1e30f;
        if (k0 + 63 <= q0 + wr0) {
#pragma unroll
            for (int j = 0; j < 8; j++) {
                float s0 = cs[j][0] * SCALE;
                float s1 = cs[j][1] * SCALE;
                float s2 = cs[j][2] * SCALE;
                float s3 = cs[j][3] * SCALE;
                cs[j][0] = s0; cs[j][1] = s1; cs[j][2] = s2; cs[j][3] = s3;
                mx0 = fmaxf(mx0, fmaxf(s0, s1));
                mx1 = fmaxf(mx1, fmaxf(s2, s3));
            }
        } else {
#pragma unroll
            for (int j = 0; j < 8; j++) {
                int gc0 = k0 + 8 * j + 2 * tg;
                int gc1 = gc0 + 1;
                float s0 = cs[j][0] * SCALE; if (gc0 > gr0) s0 = -1e30f;
                float s1 = cs[j][1] * SCALE; if (gc1 > gr0) s1 = -1e30f;
                float s2 = cs[j][2] * SCALE; if (gc0 > gr1) s2 = -1e30f;
                float s3 = cs[j][3] * SCALE; if (gc1 > gr1) s3 = -1e30f;
                cs[j][0] = s0; cs[j][1] = s1; cs[j][2] = s2; cs[j][3] = s3;
                mx0 = fmaxf(mx0, fmaxf(s0, s1));
                mx1 = fmaxf(mx1, fmaxf(s2, s3));
            }
        }
        mx0 = fmaxf(mx0, __shfl_xor_sync(0xffffffffu, mx0, 1));
        mx0 = fmaxf(mx0, __shfl_xor_sync(0xffffffffu, mx0, 2));
        mx1 = fmaxf(mx1, __shfl_xor_sync(0xffffffffu, mx1, 1));
        mx1 = fmaxf(mx1, __shfl_xor_sync(0xffffffffu, mx1, 2));

        float mn0 = fmaxf(m_prev[0], mx0);
        float mn1 = fmaxf(m_prev[1], mx1);
        float f0 = __expf(m_prev[0] - mn0);
        float f1 = __expf(m_prev[1] - mn1);
        m_prev[0] = mn0; m_prev[1] = mn1;

        uint32_t a_pv[4][4];
        float ls0 = 0.0f, ls1 = 0.0f;
#pragma unroll
        for (int s = 0; s < 4; s++) {
#pragma unroll
            for (int half = 0; half < 2; half++) {
                int j = 2 * s + half;
                float p0 = __expf(cs[j][0] - mn0);
                float p1 = __expf(cs[j][1] - mn0);
                float p2 = __expf(cs[j][2] - mn1);
                float p3 = __expf(cs[j][3] - mn1);
                ls0 += p0 + p1;
                ls1 += p2 + p3;
                a_pv[s][2 * half]     = pack_h2(p0, p1);
                a_pv[s][2 * half + 1] = pack_h2(p2, p3);
            }
        }
        ls0 += __shfl_xor_sync(0xffffffffu, ls0, 1);
        ls0 += __shfl_xor_sync(0xffffffffu, ls0, 2);
        ls1 += __shfl_xor_sync(0xffffffffu, ls1, 1);
        ls1 += __shfl_xor_sync(0xffffffffu, ls1, 2);
        l_acc[0] = l_acc[0] * f0 + ls0;
        l_acc[1] = l_acc[1] * f1 + ls1;

#pragma unroll
        for (int nj = 0; nj < 16; nj++) {
            acc[nj][0] *= f0; acc[nj][1] *= f0;
            acc[nj][2] *= f1; acc[nj][3] *= f1;
        }

#pragma unroll
        for (int s = 0; s < 4; s++) {
            const uint32_t vsbase = sV + (uint32_t)(s * 16 * AQW * 4);
#pragma unroll
            for (int v = 0; v < 8; v++) {
                uint32_t bq[4];
                ldsm_x4_t(bq, vsbase + vOff[v]);
                mma_h(acc[2 * v],     a_pv[s], &bq[0]);
                mma_h(acc[2 * v + 1], a_pv[s], &bq[2]);
            }
        }
    }

    float inv0 = 1.0f / l_acc[0];
    float inv1 = 1.0f / l_acc[1];
    size_t row0 = (size_t)(b * TT + q0 + wr0 + g);
    size_t row1 = row0 + 8;
#pragma unroll
    for (int nj = 0; nj < 16; nj++) {
        int col = h * DH + 8 * nj + 2 * tg;
        *(uint32_t*)(y + row0 * CC + col) = pack_h2(acc[nj][0] * inv0, acc[nj][1] * inv0);
        *(uint32_t*)(y + row1 * CC + col) = pack_h2(acc[nj][2] * inv1, acc[nj][3] * inv1);
    }
}

// ---------------------------------------------------------------------------
extern "C" void kernel_launch(void* const* d_in, const int* in_sizes, int n_in,
                              void* d_out, int out_size) {
    (void)in_sizes; (void)n_in; (void)out_size;
    const float* x      = (const float*)d_in[0];
    const float* W_attn = (const float*)d_in[2];
    const float* b_attn = (const float*)d_in[3];
    const float* W_proj = (const float*)d_in[4];
    const float* b_proj = (const float*)d_in[5];

    float* out   = (float*)d_out;
    float* y_out = out;
    float* cache = out + (size_t)M_ROWS * CC;

    __half *xh, *qkvh, *yh, *wah, *wph;
    cudaGetSymbolAddress((void**)&xh,   g_xh);
    cudaGetSymbolAddress((void**)&qkvh, g_qkvh);
    cudaGetSymbolAddress((void**)&yh,   g_yh);
    cudaGetSymbolAddress((void**)&wah,  g_wah);
    cudaGetSymbolAddress((void**)&wph,  g_wph);

    cudaFuncSetAttribute(h_gemm_kernel,
                         cudaFuncAttributeMaxDynamicSharedMemorySize, GEMM_SMEM);
    cudaFuncSetAttribute(attn_h_kernel,
                         cudaFuncAttributeMaxDynamicSharedMemorySize, ATTN_SMEM_BYTES);

    // 0) pre-pass: elementwise f32->f16 (no transposes)
    f2h_kernel<<<(int)((size_t)M_ROWS * CC / 4 / 256), 256>>>(x, xh);
    f2h_kernel<<<(int)((size_t)CC * QKV_N / 4 / 256), 256>>>(W_attn, wah);
    f2h_kernel<<<(int)((size_t)CC * CC / 4 / 256), 256>>>(W_proj, wph);

    // 1) qkv = x @ W_attn + b_attn -> qkv fp16 + fused f32 cache
    {
        dim3 grid(QKV_N / GBN, M_ROWS / GBM);   // (48, 32)
        h_gemm_kernel<<<grid, 256, GEMM_SMEM>>>(xh, wah, b_attn,
                                                nullptr, qkvh, cache,
                                                M_ROWS, QKV_N, CC);
    }
    // 2) flash attention fp16 -> yh
    {
        dim3 grid(BB * HH, TT / 128);           // (32, 16)
        attn_h_kernel<<<grid, 256, ATTN_SMEM_BYTES>>>(qkvh, yh);
    }
    // 3) y = yh @ W_proj + b_proj -> f32 out
    {
        dim3 grid(CC / GBN, M_ROWS / GBM);      // (16, 32)
        h_gemm_kernel<<<grid, 256, GEMM_SMEM>>>(yh, wph, b_proj,
                                                y_out, nullptr, nullptr,
                                                M_ROWS, CC, CC);
    }
}